// round 2
// baseline (speedup 1.0000x reference)
#include <cuda_runtime.h>
#include <math.h>
#include <stdint.h>
#include <stddef.h>

// ---------------------------------------------------------------------------
// AugmentedLstm: B=64, T=512, D=512, H=512
//   Kernel A: proj = X[32768,512] @ w_in^T -> [32768,3072] (+bias), fp32 FFMA2
//   Kernel B: persistent 128-CTA recurrence, 512 steps, spin grid barrier
// ---------------------------------------------------------------------------

#define BDIM 64
#define TDIM 512
#define HDIM 512
#define MTOT (BDIM * TDIM)   // 32768
#define NTOT (6 * HDIM)      // 3072
#define NCTA_B 128

// packed fp32x2 FMA (sm_100+/sm_103a PTX; ptxas never emits it from C++)
#define FMA2(d, a, b) asm("fma.rn.f32x2 %0, %1, %2, %0;" : "+l"(d) : "l"(a), "l"(b))

__device__ __forceinline__ float f2lo(unsigned long long v) {
    return __uint_as_float((unsigned)(v & 0xffffffffull));
}
__device__ __forceinline__ float f2hi(unsigned long long v) {
    return __uint_as_float((unsigned)(v >> 32));
}
__device__ __forceinline__ float sigm(float x) { return 1.0f / (1.0f + expf(-x)); }

// ---- global scratch (no runtime allocation allowed) ----
__device__ float g_proj[(size_t)MTOT * NTOT];     // 402 MB input projections
__device__ float g_hbuf[2][BDIM * HDIM];          // double-buffered h state
__device__ unsigned int g_bar;                    // grid barrier counter

// lengths may arrive as int64 or int32 (jax x64 ambiguity). All lengths >= 1,
// so for int64 the second 32-bit word is 0.
__device__ __forceinline__ int read_len(const int* L, int b) {
    return (L[1] == 0) ? L[2 * b] : L[b];
}

// ---------------------------------------------------------------------------
// Kernel A: 128x128 tile SGEMM with FFMA2 (A duplicated in SMEM so a2=(a,a))
// ---------------------------------------------------------------------------
__global__ __launch_bounds__(256)
void proj_kernel(const float* __restrict__ X, const int* __restrict__ L,
                 const float* __restrict__ W, const float* __restrict__ Bi)
{
    __shared__ float As2[32 * 256];   // [k][2*m] duplicated pairs
    __shared__ float Bs[32 * 128];    // [k][n]
    const int n0 = blockIdx.x * 128;
    const int m0 = blockIdx.y * 128;
    const int bidx = m0 >> 9;         // batch of this M tile (512 % 128 == 0)
    const int t0 = m0 & 511;
    if (read_len(L, bidx) <= t0) return;   // whole tile past this batch's length

    const int tid = threadIdx.x;
    const int tm = tid >> 4;          // 0..15
    const int tn = tid & 15;          // 0..15

    unsigned long long acc[8][4] = {};

    float4 ra[4], rb[4];
    #pragma unroll
    for (int i = 0; i < 4; i++) {     // prime chunk 0
        int idx4 = tid + (i << 8);
        int rr = idx4 >> 3, kq = idx4 & 7;
        ra[i] = *(const float4*)&X[(size_t)(m0 + rr) * 512 + (kq << 2)];
        rb[i] = *(const float4*)&W[(size_t)(n0 + rr) * 512 + (kq << 2)];
    }

    for (int kc = 0; kc < 16; kc++) {
        __syncthreads();
        #pragma unroll
        for (int i = 0; i < 4; i++) {
            int idx4 = tid + (i << 8);
            int rr = idx4 >> 3, kq = idx4 & 7;
            float4 v = ra[i];
            float2 d;
            d.x = v.x; d.y = v.x; *(float2*)&As2[((kq << 2) + 0) * 256 + 2 * rr] = d;
            d.x = v.y; d.y = v.y; *(float2*)&As2[((kq << 2) + 1) * 256 + 2 * rr] = d;
            d.x = v.z; d.y = v.z; *(float2*)&As2[((kq << 2) + 2) * 256 + 2 * rr] = d;
            d.x = v.w; d.y = v.w; *(float2*)&As2[((kq << 2) + 3) * 256 + 2 * rr] = d;
            float4 w4 = rb[i];
            Bs[((kq << 2) + 0) * 128 + rr] = w4.x;
            Bs[((kq << 2) + 1) * 128 + rr] = w4.y;
            Bs[((kq << 2) + 2) * 128 + rr] = w4.z;
            Bs[((kq << 2) + 3) * 128 + rr] = w4.w;
        }
        __syncthreads();
        if (kc < 15) {   // prefetch next chunk into registers during compute
            int kb = (kc + 1) << 5;
            #pragma unroll
            for (int i = 0; i < 4; i++) {
                int idx4 = tid + (i << 8);
                int rr = idx4 >> 3, kq = idx4 & 7;
                ra[i] = *(const float4*)&X[(size_t)(m0 + rr) * 512 + kb + (kq << 2)];
                rb[i] = *(const float4*)&W[(size_t)(n0 + rr) * 512 + kb + (kq << 2)];
            }
        }
        #pragma unroll 4
        for (int k = 0; k < 32; k++) {
            unsigned long long av[8], bv[4];
            ulonglong2 q;
            q = *(const ulonglong2*)&As2[k * 256 + tm * 16 + 0];  av[0] = q.x; av[1] = q.y;
            q = *(const ulonglong2*)&As2[k * 256 + tm * 16 + 4];  av[2] = q.x; av[3] = q.y;
            q = *(const ulonglong2*)&As2[k * 256 + tm * 16 + 8];  av[4] = q.x; av[5] = q.y;
            q = *(const ulonglong2*)&As2[k * 256 + tm * 16 + 12]; av[6] = q.x; av[7] = q.y;
            q = *(const ulonglong2*)&Bs[k * 128 + tn * 8 + 0];    bv[0] = q.x; bv[1] = q.y;
            q = *(const ulonglong2*)&Bs[k * 128 + tn * 8 + 4];    bv[2] = q.x; bv[3] = q.y;
            #pragma unroll
            for (int i = 0; i < 8; i++) {
                #pragma unroll
                for (int j = 0; j < 4; j++) FMA2(acc[i][j], av[i], bv[j]);
            }
        }
    }

    float4 bb0 = *(const float4*)&Bi[n0 + tn * 8];
    float4 bb1 = *(const float4*)&Bi[n0 + tn * 8 + 4];
    #pragma unroll
    for (int i = 0; i < 8; i++) {
        float* dst = &g_proj[(size_t)(m0 + tm * 8 + i) * NTOT + n0 + tn * 8];
        float4 o0, o1;
        o0.x = f2lo(acc[i][0]) + bb0.x; o0.y = f2hi(acc[i][0]) + bb0.y;
        o0.z = f2lo(acc[i][1]) + bb0.z; o0.w = f2hi(acc[i][1]) + bb0.w;
        o1.x = f2lo(acc[i][2]) + bb1.x; o1.y = f2hi(acc[i][2]) + bb1.y;
        o1.z = f2lo(acc[i][3]) + bb1.z; o1.w = f2hi(acc[i][3]) + bb1.w;
        *(float4*)dst = o0;
        *(float4*)(dst + 4) = o1;
    }
}

// ---------------------------------------------------------------------------
// Kernel B: persistent recurrence. CTA cid owns output columns J=cid*4..cid*4+3
// (20 w_state rows resident in SMEM). Thread (b=tid/4, jl=tid%3bits) computes
// all 5 gate dots for (b, J). h broadcast via global double buffer + spin barrier.
// ---------------------------------------------------------------------------
#define SH_HSTRIDE 516   // 516 % 32 == 4 -> conflict-free h reads
#define SH_WSTRIDE 520   // 520 % 32 == 8 -> conflict-free w reads (4 jl lanes)

__global__ __launch_bounds__(256, 1)
void lstm_kernel(const int* __restrict__ L, const float* __restrict__ Ws,
                 const float* __restrict__ bs, float* __restrict__ out)
{
    extern __shared__ float sm[];
    float* sh_h = sm;                              // 64 * 516
    float* sh_w = sm + BDIM * SH_HSTRIDE;          // 20 * 520
    int* sh_len = (int*)(sh_w + 20 * SH_WSTRIDE);  // 64

    const int cid = blockIdx.x;        // 0..127
    const int tid = threadIdx.x;       // 0..255
    const int b = tid >> 2;
    const int jl = tid & 3;
    const int J = (cid << 2) + jl;

    if (tid < BDIM) sh_len[tid] = read_len(L, tid);
    for (int i = tid; i < BDIM * SH_HSTRIDE; i += 256) sh_h[i] = 0.0f;
    // 20 w_state rows: local row r = g*4 + jl  ->  global row g*512 + cid*4 + jl
    for (int idx4 = tid; idx4 < 20 * 128; idx4 += 256) {
        int r = idx4 >> 7;
        int k = (idx4 & 127) << 2;
        int grow = ((r >> 2) << 9) + (cid << 2) + (r & 3);
        *(float4*)&sh_w[r * SH_WSTRIDE + k] = *(const float4*)&Ws[(size_t)grow * 512 + k];
    }
    __syncthreads();

    const int my_len = sh_len[b];
    float bias[5];
    #pragma unroll
    for (int g = 0; g < 5; g++) bias[g] = bs[g * 512 + J];
    float c_reg = 0.0f;

    for (int t = 0; t < TDIM; t++) {
        const bool active = (t < my_len);

        // prefetch input projections for this step (independent of h)
        float pi[6];
        if (active) {
            const float* p = &g_proj[(size_t)((b << 9) + t) * NTOT + J];
            #pragma unroll
            for (int g = 0; g < 6; g++) pi[g] = p[g * 512];
        }

        // stage h into SMEM (only rows still alive; dead rows stay zero/stale-unused)
        if (t > 0) {
            #pragma unroll 4
            for (int i = 0; i < 32; i++) {
                int idx4 = tid + (i << 8);
                int bb = idx4 >> 7;
                if (sh_len[bb] > t) {
                    int k = (idx4 & 127) << 2;
                    *(float4*)&sh_h[bb * SH_HSTRIDE + k] =
                        *(const float4*)&g_hbuf[t & 1][(bb << 9) + k];
                }
            }
        }
        __syncthreads();

        unsigned long long acc[5];
        #pragma unroll
        for (int g = 0; g < 5; g++)
            acc[g] = (unsigned long long)__float_as_uint(bias[g]);  // lo=bias, hi=0

        if (active) {
            const float* hrow = &sh_h[b * SH_HSTRIDE];
            #pragma unroll 4
            for (int k = 0; k < 512; k += 4) {
                ulonglong2 hv = *(const ulonglong2*)&hrow[k];
                #pragma unroll
                for (int g = 0; g < 5; g++) {
                    ulonglong2 wv = *(const ulonglong2*)&sh_w[(g * 4 + jl) * SH_WSTRIDE + k];
                    FMA2(acc[g], hv.x, wv.x);
                    FMA2(acc[g], hv.y, wv.y);
                }
            }
        }

        float outv = 0.0f;
        if (active) {
            float ps[5];
            #pragma unroll
            for (int g = 0; g < 5; g++) ps[g] = f2lo(acc[g]) + f2hi(acc[g]);
            float ig = sigm(pi[0] + ps[0]);
            float fg = sigm(pi[1] + ps[1]);
            float gg = tanhf(pi[2] + ps[2]);
            float og = sigm(pi[3] + ps[3]);
            float cn = ig * gg + fg * c_reg;
            float ov = og * tanhf(cn);
            float hw = sigm(pi[4] + ps[4]);
            outv = hw * ov + (1.0f - hw) * pi[5];
            c_reg = cn;
            g_hbuf[(t + 1) & 1][(b << 9) + J] = outv;
        } else {
            c_reg = 0.0f;
        }
        out[(size_t)((b << 9) + t) * HDIM + J] = outv;   // zeros past length

        if (t != TDIM - 1) {
            __threadfence();
            __syncthreads();
            if (tid == 0) {
                atomicAdd(&g_bar, 1u);
                unsigned target = (unsigned)(t + 1) * (unsigned)NCTA_B;
                while (*((volatile unsigned*)&g_bar) < target) { }
                __threadfence();
            }
            __syncthreads();
        }
    }
}

// ---------------------------------------------------------------------------
__global__ void init_kernel()
{
    int i = blockIdx.x * blockDim.x + threadIdx.x;
    if (i == 0) g_bar = 0u;
    if (i < (BDIM * HDIM) / 4) ((float4*)g_hbuf[0])[i] = make_float4(0.f, 0.f, 0.f, 0.f);
}

extern "C" void kernel_launch(void* const* d_in, const int* in_sizes, int n_in,
                              void* d_out, int out_size)
{
    const float* x       = (const float*)d_in[0];
    const int*   lengths = (const int*)d_in[1];   // int32 or int64, auto-detected
    const float* w_in    = (const float*)d_in[2];
    const float* b_in    = (const float*)d_in[3];
    const float* w_state = (const float*)d_in[4];
    const float* b_state = (const float*)d_in[5];
    float* out = (float*)d_out;

    (void)in_sizes; (void)n_in; (void)out_size;

    init_kernel<<<32, 256>>>();

    dim3 gA(NTOT / 128, MTOT / 128);  // 24 x 256
    proj_kernel<<<gA, 256>>>(x, lengths, w_in, b_in);

    size_t smemB = (size_t)(BDIM * SH_HSTRIDE + 20 * SH_WSTRIDE) * sizeof(float)
                 + BDIM * sizeof(int);
    cudaFuncSetAttribute(lstm_kernel, cudaFuncAttributeMaxDynamicSharedMemorySize,
                         (int)smemB);
    lstm_kernel<<<NCTA_B, 256, smemB>>>(lengths, w_state, b_state, out);
}